// round 9
// baseline (speedup 1.0000x reference)
#include <cuda_runtime.h>
#include <math.h>

// ---------------------------------------------------------------------------
// Problem constants
// ---------------------------------------------------------------------------
#define N_TL   32768   // timeline sequences
#define T_TL   32      // timeline seq len
#define B_SZ   512     // batch
#define T_TX   64      // text seq len
#define E_DIM  50      // embedding
#define H_DIM  32      // rnn hidden

typedef unsigned long long ull;

// ---------------------------------------------------------------------------
// Scratch (static device globals; no runtime allocation allowed)
// g_xw: precomputed x·Wi^T + bias for every (seq, t) row, both directions.
//   row layout (64 floats): position dir*32 + 2u holds col u, +1 holds col u+16
//   (interleaved so the recurrent lane reads its two values with ONE LDG.64).
// ---------------------------------------------------------------------------
#define XW_ROWS_TL ((size_t)N_TL * T_TL)
#define XW_ROWS_TX ((size_t)B_SZ * T_TX)
__device__ float g_xw[(XW_ROWS_TL + XW_ROWS_TX) * 64];
__device__ float g_h2[(size_t)N_TL * 64];   // timeline RNN final hidden [N, 2H]
__device__ float g_hn[(size_t)B_SZ * 64];   // text RNN final hidden [B, 2H]
__device__ float g_red[(size_t)B_SZ * 192]; // per-batch [mean | min | max]

// ---------------------------------------------------------------------------
// f32x2 helpers (validated R4-R7) + hardware tanh (validated R7, rel_err 4e-7)
// ---------------------------------------------------------------------------
__device__ __forceinline__ void fma2(ull& d, ull a, ull b) {
    asm("fma.rn.f32x2 %0, %1, %2, %0;" : "+l"(d) : "l"(a), "l"(b));
}
__device__ __forceinline__ ull pack2(float lo, float hi) {
    ull r; asm("mov.b64 %0, {%1, %2};" : "=l"(r) : "f"(lo), "f"(hi)); return r;
}
__device__ __forceinline__ float red2(ull a) {
    float lo, hi;
    asm("mov.b64 {%0, %1}, %2;" : "=f"(lo), "=f"(hi) : "l"(a));
    return lo + hi;
}
__device__ __forceinline__ float tanh_hw(float x) {
    float y; asm("tanh.approx.f32 %0, %1;" : "=f"(y) : "f"(x)); return y;
}
__device__ __forceinline__ float tanh_acc(float x) {   // head-precision tanh
    x = fminf(fmaxf(x, -20.0f), 20.0f);
    float e = __expf(2.0f * x);
    return __fdividef(e - 1.0f, e + 1.0f);
}

// ===========================================================================
// XW PRECOMPUTE — warp = one (seq, t) row. All lanes read the SAME x row via
// uniform-address LDG.128 (1 L1 wavefront each: gmem broadcast is free,
// unlike the smem crossbar). Lane (dir = lane>>4, u = lane&15) computes
// output cols u and u+16 of its direction with K-packed FFMA2 weights in
// registers; bias folded in. Software-pipelined: prefetch row r+stride
// while computing row r. fma-bound at ~50 FFMA2/row/lane.
// x rows are 200B apart -> 16B alignment alternates with row parity
// (validated branch pattern from R4).
// ===========================================================================
template <bool TL>
__global__ __launch_bounds__(256, 1)
void xw_kernel(const float* __restrict__ X,
               const float* __restrict__ wif, const float* __restrict__ bif,
               const float* __restrict__ bhf,
               const float* __restrict__ wib, const float* __restrict__ bib,
               const float* __restrict__ bhb,
               int nrows)
{
    const int lane = threadIdx.x & 31;
    const int half = lane >> 4;
    const int u    = lane & 15;
    const int gw     = blockIdx.x * 8 + (threadIdx.x >> 5);
    const int stride = gridDim.x * 8;

    float* XW = TL ? g_xw : (g_xw + XW_ROWS_TL * 64);

    const float* wi = half ? wib : wif;
    const float* bi = half ? bib : bif;
    const float* bh = half ? bhb : bhf;

    ull WA[25], WB[25];
#pragma unroll
    for (int q = 0; q < 25; q++) {
        WA[q] = pack2(__ldg(wi + u * E_DIM + 2 * q),        __ldg(wi + u * E_DIM + 2 * q + 1));
        WB[q] = pack2(__ldg(wi + (u + 16) * E_DIM + 2 * q), __ldg(wi + (u + 16) * E_DIM + 2 * q + 1));
    }
    const float biasA = __ldg(bi + u)      + __ldg(bh + u);
    const float biasB = __ldg(bi + u + 16) + __ldg(bh + u + 16);

    float4 qa[12]; float2 ta;
    float4 qb[12]; float2 tb;

    auto LOAD = [&](float4* q, float2& t, int r) {
        const float* rp = X + (size_t)r * E_DIM;
        if (r & 1) {
            t = __ldg(reinterpret_cast<const float2*>(rp));
            const float4* p4 = reinterpret_cast<const float4*>(rp + 2);
#pragma unroll
            for (int i = 0; i < 12; i++) q[i] = __ldg(p4 + i);
        } else {
            const float4* p4 = reinterpret_cast<const float4*>(rp);
#pragma unroll
            for (int i = 0; i < 12; i++) q[i] = __ldg(p4 + i);
            t = __ldg(reinterpret_cast<const float2*>(rp + 48));
        }
    };

    auto COMP = [&](const float4* q, const float2 t, int r) {
        ull xp[25];
        if (r & 1) {
            xp[0] = pack2(t.x, t.y);
#pragma unroll
            for (int i = 0; i < 12; i++) {
                xp[1 + 2 * i] = pack2(q[i].x, q[i].y);
                xp[2 + 2 * i] = pack2(q[i].z, q[i].w);
            }
        } else {
#pragma unroll
            for (int i = 0; i < 12; i++) {
                xp[2 * i]     = pack2(q[i].x, q[i].y);
                xp[2 * i + 1] = pack2(q[i].z, q[i].w);
            }
            xp[24] = pack2(t.x, t.y);
        }
        ull aA0 = pack2(biasA, 0.0f), aA1 = 0ULL;
        ull aB0 = pack2(biasB, 0.0f), aB1 = 0ULL;
#pragma unroll
        for (int p = 0; p < 25; p++) {
            if (p & 1) { fma2(aA1, xp[p], WA[p]); fma2(aB1, xp[p], WB[p]); }
            else       { fma2(aA0, xp[p], WA[p]); fma2(aB0, xp[p], WB[p]); }
        }
        float2 o = make_float2(red2(aA0) + red2(aA1), red2(aB0) + red2(aB1));
        *reinterpret_cast<float2*>(XW + (size_t)r * 64 + half * 32 + 2 * u) = o;
    };

    int r = gw;
    if (r < nrows) LOAD(qa, ta, r);
    while (r < nrows) {
        int rn = r + stride;
        if (rn < nrows) LOAD(qb, tb, rn);   // prefetch (overlaps compute)
        COMP(qa, ta, r);
        r = rn;
        if (r >= nrows) break;
        rn = r + stride;
        if (rn < nrows) LOAD(qa, ta, rn);
        COMP(qb, tb, r);
        r = rn;
    }
}

// ===========================================================================
// RECURRENT KERNEL — warp = one sequence, both directions (R7's validated
// lane/banking layout). Per step: prefetched LDG.64 of the lane's xw pair
// (already includes x·Wi^T + bias), 8 LDS.128 h broadcasts (dual-parity
// buffer, conflict-free), 32 FFMA2, 2 MUFU.TANH. LDS per warp-step drops
// from 84 SM-cyc (R7) to ~36.
// ===========================================================================
template <int T, bool TL>
__global__ __launch_bounds__(256)
void rec_kernel(const float* __restrict__ whf, const float* __restrict__ whb)
{
    __shared__ __align__(16) float hsm[8][144];   // per warp: [parity*72 + dir*36 + unit]
    const int w    = threadIdx.x >> 5;
    const int lane = threadIdx.x & 31;
    const int half = lane >> 4;
    const int u    = lane & 15;
    const int dofs = half * 36;
    const int n    = blockIdx.x * 8 + w;

    const float* XW = TL ? g_xw : (g_xw + XW_ROWS_TL * 64);

    const float* wh = half ? whb : whf;
    ull WhA[16], WhB[16];
#pragma unroll
    for (int q = 0; q < 16; q++) {
        WhA[q] = pack2(__ldg(wh + u * H_DIM + 2 * q),        __ldg(wh + u * H_DIM + 2 * q + 1));
        WhB[q] = pack2(__ldg(wh + (u + 16) * H_DIM + 2 * q), __ldg(wh + (u + 16) * H_DIM + 2 * q + 1));
    }

    float* hw = hsm[w];
    hw[dofs + u]      = 0.0f;
    hw[dofs + u + 16] = 0.0f;
    __syncwarp();

    const float* xwp = XW + (size_t)n * T * 64 + half * 32 + 2 * u;
    float2 xv = *reinterpret_cast<const float2*>(xwp + (half ? (T - 1) * 64 : 0));
    float h0 = 0.0f, h1 = 0.0f;

#pragma unroll 1
    for (int s = 0; s < T; s++) {
        const int p = s & 1;
        float2 xn = xv;
        if (s + 1 < T) {
            const int rtn = half ? (T - 2 - s) : (s + 1);
            xn = *reinterpret_cast<const float2*>(xwp + rtn * 64);   // prefetch
        }

        ull aA0 = pack2(xv.x, 0.0f), aA1 = 0ULL;
        ull aB0 = pack2(xv.y, 0.0f), aB1 = 0ULL;
        const float4* hr = reinterpret_cast<const float4*>(hw + p * 72 + dofs);
#pragma unroll
        for (int q = 0; q < 8; q++) {
            float4 v = hr[q];
            ull lo = pack2(v.x, v.y);
            ull hi = pack2(v.z, v.w);
            fma2(aA0, lo, WhA[2 * q]);
            fma2(aA1, hi, WhA[2 * q + 1]);
            fma2(aB0, lo, WhB[2 * q]);
            fma2(aB1, hi, WhB[2 * q + 1]);
        }
        h0 = tanh_hw(red2(aA0) + red2(aA1));
        h1 = tanh_hw(red2(aB0) + red2(aB1));
        hw[(p ^ 1) * 72 + dofs + u]      = h0;
        hw[(p ^ 1) * 72 + dofs + u + 16] = h1;
        __syncwarp();
        xv = xn;
    }

    float* op = TL ? g_h2 : g_hn;
    op[(size_t)n * 64 + half * 32 + u]      = h0;
    op[(size_t)n * 64 + half * 32 + u + 16] = h1;
}

// ---------------------------------------------------------------------------
// Ragged segment mean/min/max over g_h2 (validated R2-R7)
// ---------------------------------------------------------------------------
__global__ void seg_reduce_kernel(const int* __restrict__ te)
{
    const int b = blockIdx.x;
    const int c = threadIdx.x;   // 0..63
    __shared__ int s_off;
    if (c == 0) {
        int o = 0;
        for (int i = 0; i < b; i++) o += te[i];
        s_off = o;
    }
    __syncthreads();
    const int cnt = te[b];
    const float* hp = g_h2 + (size_t)s_off * 64 + c;
    float sm = 0.0f, mn = 3.402823466e38f, mx = -3.402823466e38f;
    for (int r = 0; r < cnt; r++) {
        float v = hp[(size_t)r * 64];
        sm += v;
        mn = fminf(mn, v);
        mx = fmaxf(mx, v);
    }
    const float inv = (cnt > 0) ? __fdividef(1.0f, (float)cnt) : 0.0f;
    g_red[b * 192 + c]       = sm * inv;
    g_red[b * 192 + 64 + c]  = mn;
    g_red[b * 192 + 128 + c] = mx;
}

// ---------------------------------------------------------------------------
// Head (validated R3-R7): one block per batch row, coalesced fc1 dots.
// ---------------------------------------------------------------------------
__global__ __launch_bounds__(128)
void head_kernel(const float* __restrict__ nf,
                 const float* __restrict__ fc1_w, const float* __restrict__ fc1_b,
                 const float* __restrict__ fc2_w, const float* __restrict__ fc2_b,
                 float* __restrict__ out)
{
    __shared__ float xv[305];
    __shared__ float yp[4];
    const int row  = blockIdx.x;
    const int tid  = threadIdx.x;
    const int w    = tid >> 5;
    const int lane = tid & 31;

    for (int i = tid; i < 305; i += 128) {
        float v;
        if (i < 64)        v = g_hn[(size_t)row * 64 + i];
        else if (i < 113)  v = nf[(size_t)row * 49 + (i - 64)];
        else               v = g_red[(size_t)row * 192 + (i - 113)];
        xv[i] = v;
    }
    __syncthreads();

    float acc = 0.0f;
#pragma unroll
    for (int uu = 0; uu < 8; uu++) {
        const int u = w * 8 + uu;
        const float* wr = fc1_w + (size_t)u * 305;
        float ps = 0.0f;
        for (int k = lane; k < 305; k += 32)
            ps = fmaf(__ldg(wr + k), xv[k], ps);
#pragma unroll
        for (int o = 16; o > 0; o >>= 1) ps += __shfl_xor_sync(0xffffffffu, ps, o);
        if (lane == 0) {
            float y = tanh_acc(ps + __ldg(fc1_b + u));
            acc = fmaf(y, __ldg(fc2_w + u), acc);
        }
    }
    if (lane == 0) yp[w] = acc;
    __syncthreads();
    if (tid == 0) {
        float z = yp[0] + yp[1] + yp[2] + yp[3] + __ldg(fc2_b);
        out[row] = __fdividef(1.0f, 1.0f + __expf(-z));
    }
}

// ---------------------------------------------------------------------------
// Launch. Runtime input-ordering detection (validated R2-R7).
// Pure kernel launches — graph-capturable, allocation-free.
// Per-rnn input layout: wif, whf, bif, bhf, wib, whb, bib, bhb.
// ---------------------------------------------------------------------------
extern "C" void kernel_launch(void* const* d_in, const int* in_sizes, int n_in,
                              void* d_out, int out_size)
{
    int base_r1, base_r2, base_fc, idx_te;
    if (in_sizes[3] == B_SZ) {          // setup_inputs order
        idx_te = 3;  base_r1 = 4;  base_r2 = 12; base_fc = 20;
    } else {                            // reference signature order
        base_r1 = 3; base_r2 = 11; base_fc = 19; idx_te = n_in - 1;
    }

    const float* nf  = (const float*)d_in[0];
    const float* tf  = (const float*)d_in[1];
    const float* ttf = (const float*)d_in[2];
    const int*   te  = (const int*)d_in[idx_te];
#define FPTR(i) ((const float*)d_in[(i)])

    // 1) xw precompute: timeline (1.05M rows) then text (32K rows).
    xw_kernel<true><<<296, 256>>>(
        ttf,
        FPTR(base_r2 + 0), FPTR(base_r2 + 2), FPTR(base_r2 + 3),   // wif, bif, bhf
        FPTR(base_r2 + 4), FPTR(base_r2 + 6), FPTR(base_r2 + 7),   // wib, bib, bhb
        (int)XW_ROWS_TL);
    xw_kernel<false><<<64, 256>>>(
        tf,
        FPTR(base_r1 + 0), FPTR(base_r1 + 2), FPTR(base_r1 + 3),
        FPTR(base_r1 + 4), FPTR(base_r1 + 6), FPTR(base_r1 + 7),
        (int)XW_ROWS_TX);

    // 2) recurrences (h·Wh^T only), warp per sequence.
    rec_kernel<T_TL, true><<<N_TL / 8, 256>>>(FPTR(base_r2 + 1), FPTR(base_r2 + 5));
    rec_kernel<T_TX, false><<<B_SZ / 8, 256>>>(FPTR(base_r1 + 1), FPTR(base_r1 + 5));

    // 3) segment mean/min/max.
    seg_reduce_kernel<<<B_SZ, 64>>>(te);

    // 4) head.
    head_kernel<<<B_SZ, 128>>>(
        nf,
        FPTR(base_fc + 0), FPTR(base_fc + 1), FPTR(base_fc + 2), FPTR(base_fc + 3),
        (float*)d_out);
#undef FPTR
}

// round 12
// speedup vs baseline: 2.3124x; 2.3124x over previous
#include <cuda_runtime.h>
#include <math.h>

// ---------------------------------------------------------------------------
// Problem constants
// ---------------------------------------------------------------------------
#define N_TL   32768   // timeline sequences
#define T_TL   32      // timeline seq len
#define B_SZ   512     // batch
#define T_TX   64      // text seq len
#define E_DIM  50      // embedding
#define H_DIM  32      // rnn hidden

typedef unsigned long long ull;

// ---------------------------------------------------------------------------
// Scratch (static device globals; no runtime allocation allowed)
// ---------------------------------------------------------------------------
__device__ float g_h2[(size_t)N_TL * 64];   // timeline RNN final hidden [N, 2H]
__device__ float g_hn[(size_t)B_SZ * 64];   // text RNN final hidden [B, 2H]
__device__ float g_red[(size_t)B_SZ * 192]; // per-batch [mean | min | max]

// ---------------------------------------------------------------------------
// f32x2 helpers (validated R4-R7) + hardware tanh (validated R7)
// ---------------------------------------------------------------------------
__device__ __forceinline__ void fma2(ull& d, ull a, ull b) {
    asm("fma.rn.f32x2 %0, %1, %2, %0;" : "+l"(d) : "l"(a), "l"(b));
}
__device__ __forceinline__ ull pack2(float lo, float hi) {
    ull r; asm("mov.b64 %0, {%1, %2};" : "=l"(r) : "f"(lo), "f"(hi)); return r;
}
__device__ __forceinline__ float red2(ull a) {
    float lo, hi;
    asm("mov.b64 {%0, %1}, %2;" : "=f"(lo), "=f"(hi) : "l"(a));
    return lo + hi;
}
__device__ __forceinline__ float tanh_hw(float x) {
    float y; asm("tanh.approx.f32 %0, %1;" : "=f"(y) : "f"(x)); return y;
}
__device__ __forceinline__ float tanh_acc(float x) {   // head-precision tanh
    x = fminf(fmaxf(x, -20.0f), 20.0f);
    float e = __expf(2.0f * x);
    return __fdividef(e - 1.0f, e + 1.0f);
}

// ===========================================================================
// TIMELINE RNN — R7 structure verbatim (warp = one sequence, both directions;
// x staged in smem rows of 56; dual-parity h broadcast buffer; 21 LDS.128 per
// step; K-packed FFMA2 weights in registers). The float4+pack2 loads are
// replaced by ulonglong2 typed loads: the 16B LDS destination register pair
// IS the pair of f32x2 operands — no repack mov.b64, no inline-asm loads.
// Persistent grid-stride, 592 blocks x 2 warps = exactly 4 blocks/SM.
// ===========================================================================
#define XROW 56
#define HSTR 36   // bwd h block offset inside a parity buffer (floats)

__global__ __launch_bounds__(64, 4)
void timeline_rnn_kernel(const float* __restrict__ X,
                         const float* __restrict__ wif, const float* __restrict__ whf,
                         const float* __restrict__ bif, const float* __restrict__ bhf,
                         const float* __restrict__ wib, const float* __restrict__ whb,
                         const float* __restrict__ bib, const float* __restrict__ bhb)
{
    __shared__ __align__(16) float xs[2][2][T_TL * XROW]; // [warp][buf][row*56]
    __shared__ __align__(16) float hsm[2][2 * 72];        // [warp][parity*72 + dir*36 + unit]

    const int lane   = threadIdx.x & 31;
    const int wlocal = threadIdx.x >> 5;          // 0..1
    const int half   = lane >> 4;                 // 0 = fwd, 1 = bwd
    const int u      = lane & 15;                 // first owned unit
    const int dofs   = half * HSTR;

    const int gwarp  = blockIdx.x * 2 + wlocal;
    const int stride = gridDim.x * 2;

    // ---- weights for this lane's direction, rows u and u+16, K-packed pairs
    const float* wi = half ? wib : wif;
    const float* wh = half ? whb : whf;
    const float* bi = half ? bib : bif;
    const float* bh = half ? bhb : bhf;

    ull WiA[26], WiB[26];
#pragma unroll
    for (int q = 0; q < 25; q++) {
        WiA[q] = pack2(__ldg(wi + u * E_DIM + 2 * q), __ldg(wi + u * E_DIM + 2 * q + 1));
        WiB[q] = pack2(__ldg(wi + (u + 16) * E_DIM + 2 * q), __ldg(wi + (u + 16) * E_DIM + 2 * q + 1));
    }
    WiA[25] = 0ULL; WiB[25] = 0ULL;               // covers zero-padded cols 50,51
    ull WhA[16], WhB[16];
#pragma unroll
    for (int q = 0; q < 16; q++) {
        WhA[q] = pack2(__ldg(wh + u * H_DIM + 2 * q), __ldg(wh + u * H_DIM + 2 * q + 1));
        WhB[q] = pack2(__ldg(wh + (u + 16) * H_DIM + 2 * q), __ldg(wh + (u + 16) * H_DIM + 2 * q + 1));
    }
    const float biasA = __ldg(bi + u)      + __ldg(bh + u);
    const float biasB = __ldg(bi + u + 16) + __ldg(bh + u + 16);

    float* xw = &xs[wlocal][0][0];
    float* hw = &hsm[wlocal][0];

    // ---- prefetch first sequence into buffer 0 (zero the 50..55 pad)
    int n = gwarp;
    if (n < N_TL) {
        const float* xg = X + (size_t)n * (T_TL * E_DIM);
        for (int i = lane; i < T_TL * XROW; i += 32) {
            int r = i / XROW, c = i - r * XROW;
            xw[i] = (c < E_DIM) ? __ldg(xg + r * E_DIM + c) : 0.0f;
        }
    }
    int buf = 0;

    for (; n < N_TL; n += stride) {
        // prefetch next sequence into the other buffer (overlaps with compute)
        int n2 = n + stride;
        if (n2 < N_TL) {
            const float* xg = X + (size_t)n2 * (T_TL * E_DIM);
            float* xd = xw + (buf ^ 1) * (T_TL * XROW);
            for (int i = lane; i < T_TL * XROW; i += 32) {
                int r = i / XROW, c = i - r * XROW;
                xd[i] = (c < E_DIM) ? __ldg(xg + r * E_DIM + c) : 0.0f;
            }
        }
        __syncwarp();

        // init h parity-0
        hw[dofs + u]      = 0.0f;
        hw[dofs + u + 16] = 0.0f;
        __syncwarp();

        const float* xb = xw + buf * (T_TL * XROW);
        float h0 = 0.0f, h1 = 0.0f;

#pragma unroll 1
        for (int s = 0; s < T_TL; s++) {
            const int p   = s & 1;
            const int row = half ? (T_TL - 1 - s) : s;   // per-half x row
            const ulonglong2* xr = reinterpret_cast<const ulonglong2*>(xb + row * XROW);
            const ulonglong2* hr = reinterpret_cast<const ulonglong2*>(hw + p * 72 + dofs);

            ull aA0 = pack2(biasA, 0.0f), aA1 = 0ULL;    // unit u
            ull aB0 = pack2(biasB, 0.0f), aB1 = 0ULL;    // unit u+16

            // x part: 13 LDS.128 (typed as u64 pairs) -> 52 FFMA2, no repacks
#pragma unroll
            for (int q = 0; q < 13; q++) {
                ulonglong2 v = xr[q];
                fma2(aA0, v.x, WiA[2 * q]);
                fma2(aA1, v.y, WiA[2 * q + 1]);
                fma2(aB0, v.x, WiB[2 * q]);
                fma2(aB1, v.y, WiB[2 * q + 1]);
            }
            // h part: 8 LDS.128 -> 32 FFMA2
#pragma unroll
            for (int q = 0; q < 8; q++) {
                ulonglong2 v = hr[q];
                fma2(aA0, v.x, WhA[2 * q]);
                fma2(aA1, v.y, WhA[2 * q + 1]);
                fma2(aB0, v.x, WhB[2 * q]);
                fma2(aB1, v.y, WhB[2 * q + 1]);
            }

            h0 = tanh_hw(red2(aA0) + red2(aA1));
            h1 = tanh_hw(red2(aB0) + red2(aB1));
            hw[(p ^ 1) * 72 + dofs + u]      = h0;
            hw[(p ^ 1) * 72 + dofs + u + 16] = h1;
            __syncwarp();
        }

        // final hidden -> [n, dir*32 + unit]
        g_h2[(size_t)n * 64 + half * 32 + u]      = h0;
        g_h2[(size_t)n * 64 + half * 32 + u + 16] = h1;
        __syncwarp();  // reads of `buf` done before next iter restages it
        buf ^= 1;
    }
}

// ===========================================================================
// TEXT RNN (1/32 of the work) — R7 design verbatim.
// ===========================================================================
template <int TSTEPS, int PAIRS>
__global__ __launch_bounds__(PAIRS * 64)
void text_rnn_kernel(const float* __restrict__ X,
                     const float* __restrict__ wif, const float* __restrict__ whf,
                     const float* __restrict__ bif, const float* __restrict__ bhf,
                     const float* __restrict__ wib, const float* __restrict__ whb,
                     const float* __restrict__ bib, const float* __restrict__ bhb,
                     int nseq)
{
    __shared__ __align__(16) float xsl[PAIRS][TSTEPS][52];
    __shared__ __align__(16) float hbuf[2][PAIRS * 2][32];

    const int tid  = threadIdx.x;
    const int w    = tid >> 5;
    const int lane = tid & 31;
    const int p    = w >> 1;
    const int dir  = w & 1;
    const int nn   = blockIdx.x * PAIRS + p;

    {
        const int q = tid - p * 64;
        const float* xg = X + (size_t)nn * (TSTEPS * E_DIM);
        for (int i = q; i < TSTEPS * 52; i += 64) {
            int t = i / 52;
            int e = i - t * 52;
            xsl[p][t][e] = (e < E_DIM) ? xg[t * E_DIM + e] : 0.0f;
        }
    }
    __syncthreads();

    const float* wi = dir ? wib : wif;
    const float* wh = dir ? whb : whf;
    const float* bi = dir ? bib : bif;
    const float* bh = dir ? bhb : bhf;

    float Wi[52];
#pragma unroll
    for (int e = 0; e < E_DIM; e++) Wi[e] = __ldg(&wi[lane * E_DIM + e]);
    Wi[50] = 0.0f; Wi[51] = 0.0f;
    float Wh[32];
#pragma unroll
    for (int k = 0; k < H_DIM; k++) Wh[k] = __ldg(&wh[lane * H_DIM + k]);
    const float bias = __ldg(&bi[lane]) + __ldg(&bh[lane]);

    float h = 0.0f;
#pragma unroll 1
    for (int s = 0; s < TSTEPS; s++) {
        const int t   = dir ? (TSTEPS - 1 - s) : s;
        const int par = s & 1;
        hbuf[par][w][lane] = h;
        __syncwarp();

        float a0 = bias, a1 = 0.0f, a2 = 0.0f, a3 = 0.0f;
        const float4* xr = reinterpret_cast<const float4*>(xsl[p][t]);
#pragma unroll
        for (int q4 = 0; q4 < 13; q4++) {
            float4 v = xr[q4];
            a0 = fmaf(v.x, Wi[4 * q4 + 0], a0);
            a1 = fmaf(v.y, Wi[4 * q4 + 1], a1);
            a2 = fmaf(v.z, Wi[4 * q4 + 2], a2);
            a3 = fmaf(v.w, Wi[4 * q4 + 3], a3);
        }
        const float4* hr = reinterpret_cast<const float4*>(hbuf[par][w]);
#pragma unroll
        for (int q4 = 0; q4 < 8; q4++) {
            float4 v = hr[q4];
            a0 = fmaf(v.x, Wh[4 * q4 + 0], a0);
            a1 = fmaf(v.y, Wh[4 * q4 + 1], a1);
            a2 = fmaf(v.z, Wh[4 * q4 + 2], a2);
            a3 = fmaf(v.w, Wh[4 * q4 + 3], a3);
        }
        h = tanh_hw((a0 + a1) + (a2 + a3));
    }

    if (nn < nseq)
        g_hn[(size_t)nn * 64 + dir * 32 + lane] = h;
}

// ---------------------------------------------------------------------------
// Ragged segment mean/min/max over g_h2 (validated R2-R9)
// ---------------------------------------------------------------------------
__global__ void seg_reduce_kernel(const int* __restrict__ te)
{
    const int b = blockIdx.x;
    const int c = threadIdx.x;   // 0..63
    __shared__ int s_off;
    if (c == 0) {
        int o = 0;
        for (int i = 0; i < b; i++) o += te[i];
        s_off = o;
    }
    __syncthreads();
    const int cnt = te[b];
    const float* hp = g_h2 + (size_t)s_off * 64 + c;
    float sm = 0.0f, mn = 3.402823466e38f, mx = -3.402823466e38f;
    for (int r = 0; r < cnt; r++) {
        float v = hp[(size_t)r * 64];
        sm += v;
        mn = fminf(mn, v);
        mx = fmaxf(mx, v);
    }
    const float inv = (cnt > 0) ? __fdividef(1.0f, (float)cnt) : 0.0f;
    g_red[b * 192 + c]       = sm * inv;
    g_red[b * 192 + 64 + c]  = mn;
    g_red[b * 192 + 128 + c] = mx;
}

// ---------------------------------------------------------------------------
// Head (validated R3-R9): one block per batch row, coalesced fc1 dots.
// ---------------------------------------------------------------------------
__global__ __launch_bounds__(128)
void head_kernel(const float* __restrict__ nf,
                 const float* __restrict__ fc1_w, const float* __restrict__ fc1_b,
                 const float* __restrict__ fc2_w, const float* __restrict__ fc2_b,
                 float* __restrict__ out)
{
    __shared__ float xv[305];
    __shared__ float yp[4];
    const int row  = blockIdx.x;
    const int tid  = threadIdx.x;
    const int w    = tid >> 5;
    const int lane = tid & 31;

    for (int i = tid; i < 305; i += 128) {
        float v;
        if (i < 64)        v = g_hn[(size_t)row * 64 + i];
        else if (i < 113)  v = nf[(size_t)row * 49 + (i - 64)];
        else               v = g_red[(size_t)row * 192 + (i - 113)];
        xv[i] = v;
    }
    __syncthreads();

    float acc = 0.0f;
#pragma unroll
    for (int uu = 0; uu < 8; uu++) {
        const int u = w * 8 + uu;
        const float* wr = fc1_w + (size_t)u * 305;
        float ps = 0.0f;
        for (int k = lane; k < 305; k += 32)
            ps = fmaf(__ldg(wr + k), xv[k], ps);
#pragma unroll
        for (int o = 16; o > 0; o >>= 1) ps += __shfl_xor_sync(0xffffffffu, ps, o);
        if (lane == 0) {
            float y = tanh_acc(ps + __ldg(fc1_b + u));
            acc = fmaf(y, __ldg(fc2_w + u), acc);
        }
    }
    if (lane == 0) yp[w] = acc;
    __syncthreads();
    if (tid == 0) {
        float z = yp[0] + yp[1] + yp[2] + yp[3] + __ldg(fc2_b);
        out[row] = __fdividef(1.0f, 1.0f + __expf(-z));
    }
}

// ---------------------------------------------------------------------------
// Launch. Runtime input-ordering detection (validated R2-R9).
// Pure kernel launches — graph-capturable, allocation-free.
// ---------------------------------------------------------------------------
extern "C" void kernel_launch(void* const* d_in, const int* in_sizes, int n_in,
                              void* d_out, int out_size)
{
    int base_r1, base_r2, base_fc, idx_te;
    if (in_sizes[3] == B_SZ) {          // setup_inputs order
        idx_te = 3;  base_r1 = 4;  base_r2 = 12; base_fc = 20;
    } else {                            // reference signature order
        base_r1 = 3; base_r2 = 11; base_fc = 19; idx_te = n_in - 1;
    }

    const float* nf  = (const float*)d_in[0];
    const float* tf  = (const float*)d_in[1];
    const float* ttf = (const float*)d_in[2];
    const int*   te  = (const int*)d_in[idx_te];
#define FPTR(i) ((const float*)d_in[(i)])

    // Timeline RNN: persistent warps, 592 blocks (exactly 4/SM) x 2 warps.
    timeline_rnn_kernel<<<592, 64>>>(
        ttf,
        FPTR(base_r2 + 0), FPTR(base_r2 + 1), FPTR(base_r2 + 2), FPTR(base_r2 + 3),
        FPTR(base_r2 + 4), FPTR(base_r2 + 5), FPTR(base_r2 + 6), FPTR(base_r2 + 7));

    // Text RNN: 512 seqs, 2 per block (4 warps), 256 blocks.
    text_rnn_kernel<T_TX, 2><<<B_SZ / 2, 128>>>(
        tf,
        FPTR(base_r1 + 0), FPTR(base_r1 + 1), FPTR(base_r1 + 2), FPTR(base_r1 + 3),
        FPTR(base_r1 + 4), FPTR(base_r1 + 5), FPTR(base_r1 + 6), FPTR(base_r1 + 7),
        B_SZ);

    // Segment mean/min/max.
    seg_reduce_kernel<<<B_SZ, 64>>>(te);

    // Head.
    head_kernel<<<B_SZ, 128>>>(
        nf,
        FPTR(base_fc + 0), FPTR(base_fc + 1), FPTR(base_fc + 2), FPTR(base_fc + 3),
        (float*)d_out);
#undef FPTR
}